// round 1
// baseline (speedup 1.0000x reference)
#include <cuda_runtime.h>
#include <cstdint>

#define Bv 128
#define Tv 4096
#define DIN 64
#define Hv 512
#define DOUT 64
#define NCTA 64
#define Uv 8            // hidden units per CTA per layer
#define NTHR 256
#define K1 576          // DIN + H
#define K2 1024         // H + H
#define K1P 580         // padded (580 % 32 == 4 -> conflict-free B-frag LDS)
#define K2P 1028
#define SMEM_BYTES ((32 * K1P + 32 * K2P + 64) * 4)

// Persistent state (allocation-free scratch per harness rules)
__device__ float g_h1[2][Bv][Hv];
__device__ float g_h2[2][Bv][Hv];
__device__ float g_c1[Bv][Hv];
__device__ float g_c2[Bv][Hv];
__device__ unsigned g_bar_count;   // zero-initialized at module load; protocol restores 0
__device__ unsigned g_bar_epoch;   // monotonic across graph replays; captured at entry

__device__ __forceinline__ unsigned f2tf(float x) {
    unsigned u;
    asm("cvt.rna.tf32.f32 %0, %1;" : "=r"(u) : "f"(x));
    return u;
}
__device__ __forceinline__ float sigm(float x) {
    return 1.0f / (1.0f + __expf(-x));
}
__device__ __forceinline__ float tanh_(float x) {
    // 1 - 2/(e^{2x}+1): correct limits at +-inf (expf overflow -> inf -> 1)
    return 1.0f - 2.0f / (__expf(2.0f * x) + 1.0f);
}

// 4 gate-group MMAs sharing one A fragment. sw rows: r = g*8 + unit_local, [r][K]
__device__ __forceinline__ void mma4(float acc[4][4], const unsigned* sw, int kpad, int kofs,
                                     unsigned a0, unsigned a1, unsigned a2, unsigned a3,
                                     int lane) {
    const int c = lane & 3, q = lane >> 2;
#pragma unroll
    for (int g = 0; g < 4; g++) {
        const unsigned* bp = sw + (g * 8 + q) * kpad + kofs + c;
        unsigned b0 = bp[0], b1 = bp[4];
        asm volatile(
            "mma.sync.aligned.m16n8k8.row.col.f32.tf32.tf32.f32 "
            "{%0,%1,%2,%3},{%4,%5,%6,%7},{%8,%9},{%0,%1,%2,%3};"
            : "+f"(acc[g][0]), "+f"(acc[g][1]), "+f"(acc[g][2]), "+f"(acc[g][3])
            : "r"(a0), "r"(a1), "r"(a2), "r"(a3), "r"(b0), "r"(b1));
    }
}

__device__ __forceinline__ void gridbar(unsigned target) {
    __syncthreads();
    if (threadIdx.x == 0) {
        __threadfence();
        unsigned old = atomicAdd(&g_bar_count, 1u);
        if (old == NCTA - 1u) {
            g_bar_count = 0u;
            __threadfence();
            *(volatile unsigned*)&g_bar_epoch = target;
        } else {
            while ((int)(*(volatile unsigned*)&g_bar_epoch - target) < 0) {}
        }
        __threadfence();
    }
    __syncthreads();
}

__global__ void __launch_bounds__(NTHR, 1)
lstm_kernel(const float* __restrict__ x,
            const float* __restrict__ w_ih1, const float* __restrict__ w_hh1,
            const float* __restrict__ b_ih1, const float* __restrict__ b_hh1,
            const float* __restrict__ w_ih2, const float* __restrict__ w_hh2,
            const float* __restrict__ b_ih2, const float* __restrict__ b_hh2,
            const float* __restrict__ w_out, const float* __restrict__ b_out,
            float* __restrict__ out) {
    extern __shared__ unsigned dynsm[];
    unsigned* sw1 = dynsm;                 // [32][K1P] tf32 bits
    unsigned* sw2 = sw1 + 32 * K1P;        // [32][K2P]
    float* sb1 = (float*)(sw2 + 32 * K2P); // [32] fused biases
    float* sb2 = sb1 + 32;
    __shared__ unsigned s_epoch0;

    const int tid = threadIdx.x;
    const int cta = blockIdx.x;
    const int lane = tid & 31;
    const int warp = tid >> 5;
    const int c4 = lane & 3;
    const int r0 = warp * 16 + (lane >> 2);
    const int r1 = r0 + 8;

    if (tid == 0) s_epoch0 = *(volatile unsigned*)&g_bar_epoch;

    // ---- stage weights (tf32-rounded) into SMEM, fuse biases ----
    for (int idx = tid; idx < 32 * K1; idx += NTHR) {
        int r = idx / K1, k = idx - r * K1;
        int j = (r >> 3) * Hv + cta * Uv + (r & 7);
        float wv = (k < DIN) ? w_ih1[j * DIN + k] : w_hh1[j * Hv + (k - DIN)];
        sw1[r * K1P + k] = f2tf(wv);
    }
    for (int idx = tid; idx < 32 * K2; idx += NTHR) {
        int r = idx >> 10, k = idx & 1023;
        int j = (r >> 3) * Hv + cta * Uv + (r & 7);
        float wv = (k < Hv) ? w_ih2[j * Hv + k] : w_hh2[j * Hv + (k - Hv)];
        sw2[r * K2P + k] = f2tf(wv);
    }
    if (tid < 32) {
        int j = (tid >> 3) * Hv + cta * Uv + (tid & 7);
        sb1[tid] = b_ih1[j] + b_hh1[j];
        sb2[tid] = b_ih2[j] + b_hh2[j];
    }
    // ---- zero initial state (h[slot 1] read at t=0; c in place) ----
    for (int idx = cta * NTHR + tid; idx < Bv * Hv; idx += NCTA * NTHR) {
        ((float*)g_h1)[Bv * Hv + idx] = 0.0f;
        ((float*)g_h2)[Bv * Hv + idx] = 0.0f;
        ((float*)g_c1)[idx] = 0.0f;
        ((float*)g_c2)[idx] = 0.0f;
    }
    __syncthreads();
    unsigned bar = s_epoch0;
    gridbar(++bar);

    for (int t = 0; t < Tv; t++) {
        const int rd = (t + 1) & 1, wr = t & 1;

        // ---- y(t-1): this CTA owns batch rows {2*cta, 2*cta+1}, all 64 cols ----
        if (t > 0 && tid < 128) {
            int col = tid & 63;
            int row = 2 * cta + (tid >> 6);
            const float* h2p = &g_h2[rd][row][0];
            const float* wo = w_out + col * Hv;
            float s = b_out[col];
#pragma unroll 8
            for (int k = 0; k < Hv; k++) s = fmaf(h2p[k], wo[k], s);
            out[((size_t)row * Tv + (t - 1)) * DOUT + col] = s;
        }

        // ---- layer1: gates[128, 32] = [x_t | h1_prev] @ W1slice^T + b ----
        {
            float acc[4][4];
#pragma unroll
            for (int g = 0; g < 4; g++) {
                float b0 = sb1[g * 8 + 2 * c4], b1 = sb1[g * 8 + 2 * c4 + 1];
                acc[g][0] = b0; acc[g][1] = b1; acc[g][2] = b0; acc[g][3] = b1;
            }
            const float* x0 = x + (size_t)t * DIN;  // + b*Tv*DIN + k
#pragma unroll 2
            for (int k0 = 0; k0 < DIN; k0 += 8) {
                unsigned a0 = f2tf(x0[(size_t)r0 * Tv * DIN + k0 + c4]);
                unsigned a1 = f2tf(x0[(size_t)r1 * Tv * DIN + k0 + c4]);
                unsigned a2 = f2tf(x0[(size_t)r0 * Tv * DIN + k0 + 4 + c4]);
                unsigned a3 = f2tf(x0[(size_t)r1 * Tv * DIN + k0 + 4 + c4]);
                mma4(acc, sw1, K1P, k0, a0, a1, a2, a3, lane);
            }
            const float* hp = &g_h1[rd][0][0];
#pragma unroll 4
            for (int k0 = 0; k0 < Hv; k0 += 8) {
                unsigned a0 = f2tf(hp[r0 * Hv + k0 + c4]);
                unsigned a1 = f2tf(hp[r1 * Hv + k0 + c4]);
                unsigned a2 = f2tf(hp[r0 * Hv + k0 + 4 + c4]);
                unsigned a3 = f2tf(hp[r1 * Hv + k0 + 4 + c4]);
                mma4(acc, sw1, K1P, DIN + k0, a0, a1, a2, a3, lane);
            }
            // epilogue: gates of one unit live in one thread (gate = reg group)
#pragma unroll
            for (int jj = 0; jj < 2; jj++) {
                int u = cta * Uv + 2 * c4 + jj;
#pragma unroll
                for (int rr = 0; rr < 2; rr++) {
                    int row = rr ? r1 : r0;
                    int q = rr * 2 + jj;
                    float iv = sigm(acc[0][q]);
                    float fv = sigm(acc[1][q]);
                    float gv = tanh_(acc[2][q]);
                    float ov = sigm(acc[3][q]);
                    float cn = fv * g_c1[row][u] + iv * gv;
                    g_c1[row][u] = cn;
                    g_h1[wr][row][u] = ov * tanh_(cn);
                }
            }
        }
        gridbar(++bar);

        // ---- layer2: gates = [h1_cur | h2_prev] @ W2slice^T + b ----
        {
            float acc[4][4];
#pragma unroll
            for (int g = 0; g < 4; g++) {
                float b0 = sb2[g * 8 + 2 * c4], b1 = sb2[g * 8 + 2 * c4 + 1];
                acc[g][0] = b0; acc[g][1] = b1; acc[g][2] = b0; acc[g][3] = b1;
            }
            const float* h1p = &g_h1[wr][0][0];
#pragma unroll 4
            for (int k0 = 0; k0 < Hv; k0 += 8) {
                unsigned a0 = f2tf(h1p[r0 * Hv + k0 + c4]);
                unsigned a1 = f2tf(h1p[r1 * Hv + k0 + c4]);
                unsigned a2 = f2tf(h1p[r0 * Hv + k0 + 4 + c4]);
                unsigned a3 = f2tf(h1p[r1 * Hv + k0 + 4 + c4]);
                mma4(acc, sw2, K2P, k0, a0, a1, a2, a3, lane);
            }
            const float* h2p = &g_h2[rd][0][0];
#pragma unroll 4
            for (int k0 = 0; k0 < Hv; k0 += 8) {
                unsigned a0 = f2tf(h2p[r0 * Hv + k0 + c4]);
                unsigned a1 = f2tf(h2p[r1 * Hv + k0 + c4]);
                unsigned a2 = f2tf(h2p[r0 * Hv + k0 + 4 + c4]);
                unsigned a3 = f2tf(h2p[r1 * Hv + k0 + 4 + c4]);
                mma4(acc, sw2, K2P, Hv + k0, a0, a1, a2, a3, lane);
            }
#pragma unroll
            for (int jj = 0; jj < 2; jj++) {
                int u = cta * Uv + 2 * c4 + jj;
#pragma unroll
                for (int rr = 0; rr < 2; rr++) {
                    int row = rr ? r1 : r0;
                    int q = rr * 2 + jj;
                    float iv = sigm(acc[0][q]);
                    float fv = sigm(acc[1][q]);
                    float gv = tanh_(acc[2][q]);
                    float ov = sigm(acc[3][q]);
                    float cn = fv * g_c2[row][u] + iv * gv;
                    g_c2[row][u] = cn;
                    g_h2[wr][row][u] = ov * tanh_(cn);
                }
            }
        }
        gridbar(++bar);
    }

    // ---- final y(T-1) (h2 slot (T-1)&1 == 1) ----
    if (tid < 128) {
        int col = tid & 63;
        int row = 2 * cta + (tid >> 6);
        const float* h2p = &g_h2[(Tv - 1) & 1][row][0];
        const float* wo = w_out + col * Hv;
        float s = b_out[col];
#pragma unroll 8
        for (int k = 0; k < Hv; k++) s = fmaf(h2p[k], wo[k], s);
        out[((size_t)row * Tv + (Tv - 1)) * DOUT + col] = s;
    }
}

extern "C" void kernel_launch(void* const* d_in, const int* in_sizes, int n_in,
                              void* d_out, int out_size) {
    (void)in_sizes; (void)n_in; (void)out_size;
    const float* x     = (const float*)d_in[0];
    const float* w_ih1 = (const float*)d_in[1];
    const float* w_hh1 = (const float*)d_in[2];
    const float* b_ih1 = (const float*)d_in[3];
    const float* b_hh1 = (const float*)d_in[4];
    const float* w_ih2 = (const float*)d_in[5];
    const float* w_hh2 = (const float*)d_in[6];
    const float* b_ih2 = (const float*)d_in[7];
    const float* b_hh2 = (const float*)d_in[8];
    const float* w_out = (const float*)d_in[9];
    const float* b_out = (const float*)d_in[10];

    cudaFuncSetAttribute(lstm_kernel, cudaFuncAttributeMaxDynamicSharedMemorySize, SMEM_BYTES);
    lstm_kernel<<<NCTA, NTHR, SMEM_BYTES>>>(x, w_ih1, w_hh1, b_ih1, b_hh1,
                                            w_ih2, w_hh2, b_ih2, b_hh2,
                                            w_out, b_out, (float*)d_out);
}

// round 2
// speedup vs baseline: 4.7163x; 4.7163x over previous
#include <cuda_runtime.h>
#include <cstdint>

#define Bv 128
#define Tv 4096
#define DIN 64
#define Hv 512
#define DOUT 64
#define NCTA 128          // 64 layer1-CTAs + 64 layer2-CTAs, all co-resident
#define NTHR 256
#define K1 576
#define K2 1024
#define K1P 580           // padded: conflict-free B-frag LDS
#define K2P 1028
#define CHW 68            // A-chunk row stride (floats); 68*4=272B=17*16 -> f4-aligned rows
#define SMEM_WORDS (2*128*CHW + 128*8 + 32 + 32*K2P)
#define SMEM_BYTES (SMEM_WORDS*4)

// Persistent scratch (static __device__ allocations are the sanctioned path)
__device__ float g_h1[2][Bv][Hv];               // layer1 h double buffer
__device__ float g_h2all[(Tv + 1)][Bv][Hv];     // full h2 history; slot 0 = zeros
__device__ unsigned g_bar_count;
__device__ unsigned g_bar_epoch;                // monotonic across replays

__device__ __forceinline__ unsigned f2tf(float x) {
    unsigned u;
    asm("cvt.rna.tf32.f32 %0, %1;" : "=r"(u) : "f"(x));
    return u;
}
__device__ __forceinline__ float sigm(float x) { return 1.0f / (1.0f + __expf(-x)); }
__device__ __forceinline__ float tanh_(float x) { return 1.0f - 2.0f / (__expf(2.0f * x) + 1.0f); }

__device__ __forceinline__ void cp16(void* sdst, const void* gsrc) {
    unsigned s = (unsigned)__cvta_generic_to_shared(sdst);
    asm volatile("cp.async.cg.shared.global [%0], [%1], 16;" :: "r"(s), "l"(gsrc));
}
__device__ __forceinline__ void cp_commit() { asm volatile("cp.async.commit_group;"); }
__device__ __forceinline__ void cp_wait1() { asm volatile("cp.async.wait_group 1;"); }
__device__ __forceinline__ void cp_wait0() { asm volatile("cp.async.wait_group 0;"); }

__device__ __forceinline__ void gridbar(unsigned target) {
    __syncthreads();
    if (threadIdx.x == 0) {
        __threadfence();
        unsigned old = atomicAdd(&g_bar_count, 1u);
        if (old == NCTA - 1u) {
            g_bar_count = 0u;
            __threadfence();
            *(volatile unsigned*)&g_bar_epoch = target;
        } else {
            while ((int)(*(volatile unsigned*)&g_bar_epoch - target) < 0) {}
        }
        __threadfence();
    }
    __syncthreads();
}

// Coalesced async copy of a 128-row x 64-col fp32 block into SMEM [128][CHW]
__device__ __forceinline__ void load_chunk(float* dst, const float* src, size_t rstride) {
#pragma unroll
    for (int i = 0; i < 8; i++) {
        int idx = i * NTHR + threadIdx.x;
        int row = idx >> 4, cq = (idx & 15) << 2;
        cp16(dst + row * CHW + cq, src + (size_t)row * rstride + cq);
    }
}

__global__ void __launch_bounds__(NTHR, 1)
lstm_kernel(const float* __restrict__ x,
            const float* __restrict__ w_ih1, const float* __restrict__ w_hh1,
            const float* __restrict__ b_ih1, const float* __restrict__ b_hh1,
            const float* __restrict__ w_ih2, const float* __restrict__ w_hh2,
            const float* __restrict__ b_ih2, const float* __restrict__ b_hh2) {
    extern __shared__ float smf[];
    float* chunk0 = smf;                       // [128][CHW]
    float* chunk1 = smf + 128 * CHW;
    float* sc = smf + 2 * 128 * CHW;           // c-state [128][8]
    float* sb = sc + 128 * 8;                  // fused biases [32]
    unsigned* sw = (unsigned*)(sb + 32);       // weights tf32 [32][K1P|K2P]
    __shared__ unsigned s_epoch0;

    const int tid = threadIdx.x;
    const bool isL2 = blockIdx.x >= 64;
    const int u0 = (blockIdx.x & 63) * 8;      // first hidden unit owned
    const int lane = tid & 31, warp = tid >> 5;
    const int c4 = lane & 3, q = lane >> 2;
    const int r0 = warp * 16 + q, r1 = r0 + 8;
    const int KP = isL2 ? K2P : K1P;

    if (tid == 0) s_epoch0 = *(volatile unsigned*)&g_bar_epoch;

    // ---- stage this CTA's weight slice (tf32-rounded) + fused biases ----
    if (!isL2) {
        for (int idx = tid; idx < 32 * K1; idx += NTHR) {
            int r = idx / K1, k = idx - r * K1;
            int j = (r >> 3) * Hv + u0 + (r & 7);
            float wv = (k < DIN) ? w_ih1[j * DIN + k] : w_hh1[(size_t)j * Hv + (k - DIN)];
            sw[r * K1P + k] = f2tf(wv);
        }
        if (tid < 32) {
            int j = (tid >> 3) * Hv + u0 + (tid & 7);
            sb[tid] = b_ih1[j] + b_hh1[j];
        }
    } else {
        for (int idx = tid; idx < 32 * K2; idx += NTHR) {
            int r = idx >> 10, k = idx & 1023;
            int j = (r >> 3) * Hv + u0 + (r & 7);
            float wv = (k < Hv) ? w_ih2[(size_t)j * Hv + k] : w_hh2[(size_t)j * Hv + (k - Hv)];
            sw[r * K2P + k] = f2tf(wv);
        }
        if (tid < 32) {
            int j = (tid >> 3) * Hv + u0 + (tid & 7);
            sb[tid] = b_ih2[j] + b_hh2[j];
        }
    }
    for (int i = tid; i < 128 * 8; i += NTHR) sc[i] = 0.0f;

    // ---- zero shared initial state: g_h1 slot 1, g_h2all slot 0 ----
    for (int idx = blockIdx.x * NTHR + tid; idx < Bv * Hv; idx += NCTA * NTHR) {
        ((float*)g_h1)[Bv * Hv + idx] = 0.0f;
        ((float*)g_h2all)[idx] = 0.0f;
    }
    __syncthreads();
    unsigned bar = s_epoch0;
    gridbar(++bar);

    // ---- pipelined recurrence: phase p: L1 computes h1(p), L2 computes h2(p-1) ----
    for (int p = 0; p <= Tv; p++) {
        const bool active = isL2 ? (p >= 1) : (p < Tv);
        if (active) {
            float acc[4][4];
#pragma unroll
            for (int g = 0; g < 4; g++) {
                float b0 = sb[g * 8 + 2 * c4], b1 = sb[g * 8 + 2 * c4 + 1];
                acc[g][0] = b0; acc[g][1] = b1; acc[g][2] = b0; acc[g][3] = b1;
            }
            const int NCH = isL2 ? 16 : 9;
            const float* srcA;  // L1: x(:,p,:) ; L2: h1(p-1)
            const float* srcB;  // L1: h1(p-1)  ; L2: h2(p-2)
            if (isL2) { srcA = &g_h1[(p - 1) & 1][0][0]; srcB = &g_h2all[p - 1][0][0]; }
            else      { srcA = x + (size_t)p * DIN;      srcB = &g_h1[(p - 1) & 1][0][0]; }

            // prologue: chunk 0
            if (!isL2) load_chunk(chunk0, srcA, (size_t)Tv * DIN);
            else       load_chunk(chunk0, srcA, Hv);
            cp_commit();

            for (int c = 0; c < NCH; c++) {
                if (c + 1 < NCH) {
                    const float* s; size_t st;
                    int cn = c + 1;
                    if (!isL2) {
                        if (cn == 0) { s = srcA; st = (size_t)Tv * DIN; }
                        else { s = srcB + (cn - 1) * 64; st = Hv; }
                    } else {
                        if (cn < 8) { s = srcA + cn * 64; st = Hv; }
                        else { s = srcB + (cn - 8) * 64; st = Hv; }
                    }
                    load_chunk((c & 1) ? chunk0 : chunk1, s, st);
                    cp_commit();
                    cp_wait1();
                } else {
                    cp_wait0();
                }
                __syncthreads();
                const float* buf = (c & 1) ? chunk1 : chunk0;
                const float* ap = buf + r0 * CHW + c4;
                const int kb = c * 64;
#pragma unroll
                for (int kc = 0; kc < 64; kc += 8) {
                    unsigned a0 = f2tf(ap[kc]);
                    unsigned a1 = f2tf(ap[kc + 8 * CHW]);
                    unsigned a2 = f2tf(ap[kc + 4]);
                    unsigned a3 = f2tf(ap[kc + 4 + 8 * CHW]);
#pragma unroll
                    for (int g = 0; g < 4; g++) {
                        const unsigned* bp = sw + (g * 8 + q) * KP + kb + kc + c4;
                        unsigned b0 = bp[0], b1 = bp[4];
                        asm volatile(
                            "mma.sync.aligned.m16n8k8.row.col.f32.tf32.tf32.f32 "
                            "{%0,%1,%2,%3},{%4,%5,%6,%7},{%8,%9},{%0,%1,%2,%3};"
                            : "+f"(acc[g][0]), "+f"(acc[g][1]), "+f"(acc[g][2]), "+f"(acc[g][3])
                            : "r"(a0), "r"(a1), "r"(a2), "r"(a3), "r"(b0), "r"(b1));
                    }
                }
                __syncthreads();
            }

            // ---- epilogue: gate nonlinearities, c update (SMEM), h store (global) ----
            float* hout = isL2 ? &g_h2all[p][0][0] : &g_h1[p & 1][0][0];
#pragma unroll
            for (int jj = 0; jj < 2; jj++) {
                int ul = 2 * c4 + jj;
#pragma unroll
                for (int rr = 0; rr < 2; rr++) {
                    int row = rr ? r1 : r0;
                    int qi = rr * 2 + jj;
                    float iv = sigm(acc[0][qi]);
                    float fv = sigm(acc[1][qi]);
                    float gv = tanh_(acc[2][qi]);
                    float ov = sigm(acc[3][qi]);
                    float cn = fv * sc[row * 8 + ul] + iv * gv;
                    sc[row * 8 + ul] = cn;
                    hout[(size_t)row * Hv + u0 + ul] = ov * tanh_(cn);
                }
            }
        }
        gridbar(++bar);
    }
}

// Post-pass: out[b][t][o] = h2(t)[b] . w_out[o] + b_out[o], reading g_h2all slots 1..T
__global__ void __launch_bounds__(256)
out_gemm(const float* __restrict__ w_out, const float* __restrict__ b_out,
         float* __restrict__ out) {
    __shared__ __align__(16) float As[32 * CHW];  // [k][t]
    __shared__ __align__(16) float Bs[32 * CHW];  // [k][o]
    const int b = blockIdx.y;
    const int t0 = blockIdx.x * 64;
    const int tx = threadIdx.x;
    const int to = (tx & 15) * 4;
    const int tt = (tx >> 4) * 4;
    float acc[4][4] = {};
    for (int k0 = 0; k0 < Hv; k0 += 32) {
        for (int i = tx; i < 512; i += 256) {
            int row = i >> 3, kq = (i & 7) * 4;
            float4 v = *(const float4*)(&g_h2all[t0 + row + 1][b][k0 + kq]);
            As[(kq + 0) * CHW + row] = v.x;
            As[(kq + 1) * CHW + row] = v.y;
            As[(kq + 2) * CHW + row] = v.z;
            As[(kq + 3) * CHW + row] = v.w;
        }
        for (int i = tx; i < 512; i += 256) {
            int o = i >> 3, kq = (i & 7) * 4;
            float4 v = *(const float4*)(w_out + (size_t)o * Hv + k0 + kq);
            Bs[(kq + 0) * CHW + o] = v.x;
            Bs[(kq + 1) * CHW + o] = v.y;
            Bs[(kq + 2) * CHW + o] = v.z;
            Bs[(kq + 3) * CHW + o] = v.w;
        }
        __syncthreads();
#pragma unroll
        for (int k = 0; k < 32; k++) {
            float4 a = *(const float4*)(As + k * CHW + tt);
            float4 w = *(const float4*)(Bs + k * CHW + to);
            acc[0][0] = fmaf(a.x, w.x, acc[0][0]); acc[0][1] = fmaf(a.x, w.y, acc[0][1]);
            acc[0][2] = fmaf(a.x, w.z, acc[0][2]); acc[0][3] = fmaf(a.x, w.w, acc[0][3]);
            acc[1][0] = fmaf(a.y, w.x, acc[1][0]); acc[1][1] = fmaf(a.y, w.y, acc[1][1]);
            acc[1][2] = fmaf(a.y, w.z, acc[1][2]); acc[1][3] = fmaf(a.y, w.w, acc[1][3]);
            acc[2][0] = fmaf(a.z, w.x, acc[2][0]); acc[2][1] = fmaf(a.z, w.y, acc[2][1]);
            acc[2][2] = fmaf(a.z, w.z, acc[2][2]); acc[2][3] = fmaf(a.z, w.w, acc[2][3]);
            acc[3][0] = fmaf(a.w, w.x, acc[3][0]); acc[3][1] = fmaf(a.w, w.y, acc[3][1]);
            acc[3][2] = fmaf(a.w, w.z, acc[3][2]); acc[3][3] = fmaf(a.w, w.w, acc[3][3]);
        }
        __syncthreads();
    }
    float bo0 = b_out[to + 0], bo1 = b_out[to + 1], bo2 = b_out[to + 2], bo3 = b_out[to + 3];
#pragma unroll
    for (int i = 0; i < 4; i++) {
        float4 r;
        r.x = acc[i][0] + bo0; r.y = acc[i][1] + bo1;
        r.z = acc[i][2] + bo2; r.w = acc[i][3] + bo3;
        *(float4*)(out + ((size_t)b * Tv + t0 + tt + i) * DOUT + to) = r;
    }
}

extern "C" void kernel_launch(void* const* d_in, const int* in_sizes, int n_in,
                              void* d_out, int out_size) {
    (void)in_sizes; (void)n_in; (void)out_size;
    const float* x     = (const float*)d_in[0];
    const float* w_ih1 = (const float*)d_in[1];
    const float* w_hh1 = (const float*)d_in[2];
    const float* b_ih1 = (const float*)d_in[3];
    const float* b_hh1 = (const float*)d_in[4];
    const float* w_ih2 = (const float*)d_in[5];
    const float* w_hh2 = (const float*)d_in[6];
    const float* b_ih2 = (const float*)d_in[7];
    const float* b_hh2 = (const float*)d_in[8];
    const float* w_out = (const float*)d_in[9];
    const float* b_out = (const float*)d_in[10];

    cudaFuncSetAttribute(lstm_kernel, cudaFuncAttributeMaxDynamicSharedMemorySize, SMEM_BYTES);
    lstm_kernel<<<NCTA, NTHR, SMEM_BYTES>>>(x, w_ih1, w_hh1, b_ih1, b_hh1,
                                            w_ih2, w_hh2, b_ih2, b_hh2);
    out_gemm<<<dim3(Tv / 64, Bv), 256>>>(w_out, b_out, (float*)d_out);
}

// round 3
// speedup vs baseline: 6.1449x; 1.3029x over previous
#include <cuda_runtime.h>
#include <cstdint>

#define Bv 128
#define Tv 4096
#define DIN 64
#define Hv 512
#define DOUT 64
#define NCTA 128          // 64 layer1-CTAs + 64 layer2-CTAs
#define NTHR 256
#define K1 576
#define K2 1024
#define K1P 580
#define K2P 1028
#define CHW 68            // padded chunk row stride (floats) -> conflict-free LDS
#define CHUNK_W (128 * CHW)          // floats per chunk
#define CHUNK_BYTES (CHUNK_W * 4)    // 34816, multiple of 16
#define SMEM_WORDS (2 * CHUNK_W + 32 * K2P + 128 * 8 + 32 + 4)
#define SMEM_BYTES (SMEM_WORDS * 4)

// Persistent scratch (static __device__: the sanctioned allocation path)
__device__ float g_xT[(size_t)Tv * CHUNK_W];            // x transposed+padded [t][b][68]
__device__ float g_h1[2][8][128][CHW];                  // layer1 h, chunk-major
__device__ float g_h2all[(size_t)(Tv + 1) * 8 * 128 * CHW]; // h2 history, slot 0 = zeros
__device__ unsigned g_bar_count;
__device__ unsigned g_bar_epoch;                        // monotonic across replays

__device__ __forceinline__ unsigned f2tf(float x) {
    unsigned u;
    asm("cvt.rna.tf32.f32 %0, %1;" : "=r"(u) : "f"(x));
    return u;
}
__device__ __forceinline__ float sigm(float x) { return 1.0f / (1.0f + __expf(-x)); }
__device__ __forceinline__ float tanh_(float x) { return 1.0f - 2.0f / (__expf(2.0f * x) + 1.0f); }

__device__ __forceinline__ void issue_chunk(unsigned sdst, const float* gsrc, unsigned mbar) {
    asm volatile("mbarrier.arrive.expect_tx.shared.b64 _, [%0], %1;"
                 :: "r"(mbar), "r"((unsigned)CHUNK_BYTES) : "memory");
    asm volatile("cp.async.bulk.shared::cta.global.mbarrier::complete_tx::bytes [%0], [%1], %2, [%3];"
                 :: "r"(sdst), "l"(gsrc), "r"((unsigned)CHUNK_BYTES), "r"(mbar) : "memory");
}
__device__ __forceinline__ void mbar_wait(unsigned mbar, unsigned parity) {
    asm volatile(
        "{\n\t.reg .pred P;\n"
        "W%=:\n\t"
        "mbarrier.try_wait.parity.acquire.cta.shared::cta.b64 P, [%0], %1, 0x989680;\n\t"
        "@!P bra W%=;\n\t}"
        :: "r"(mbar), "r"(parity) : "memory");
}

__device__ __forceinline__ void gridbar(unsigned target) {
    __syncthreads();
    if (threadIdx.x == 0) {
        __threadfence();
        unsigned old = atomicAdd(&g_bar_count, 1u);
        if (old == NCTA - 1u) {
            g_bar_count = 0u;
            __threadfence();
            *(volatile unsigned*)&g_bar_epoch = target;
        } else {
            while ((int)(*(volatile unsigned*)&g_bar_epoch - target) < 0) {}
        }
        __threadfence();
    }
    __syncthreads();
}

// One-time x transpose: x[b][t][64] -> xT[t][b][68-padded]
__global__ void __launch_bounds__(256)
xpose(const float* __restrict__ x) {
    const int t = blockIdx.x;
    for (int i = threadIdx.x; i < 128 * 16; i += 256) {
        int b = i >> 4, j = i & 15;
        float4 v = *(const float4*)(x + ((size_t)b * Tv + t) * 64 + j * 4);
        *(float4*)(g_xT + (size_t)t * CHUNK_W + b * CHW + j * 4) = v;
    }
}

__global__ void __launch_bounds__(NTHR, 1)
lstm_kernel(const float* __restrict__ w_ih1, const float* __restrict__ w_hh1,
            const float* __restrict__ b_ih1, const float* __restrict__ b_hh1,
            const float* __restrict__ w_ih2, const float* __restrict__ w_hh2,
            const float* __restrict__ b_ih2, const float* __restrict__ b_hh2) {
    extern __shared__ float smf[];
    float* chunks = smf;                         // 2 x [128][CHW]
    unsigned* sw = (unsigned*)(smf + 2 * CHUNK_W);  // weights tf32 [32][K1P|K2P]
    float* sc = smf + 2 * CHUNK_W + 32 * K2P;    // c-state [128][8]
    float* sb = sc + 128 * 8;                    // fused biases [32]
    float* mbf = sb + 32;                        // 2 mbarriers (16B, 8-aligned)
    __shared__ unsigned s_epoch0;

    const int tid = threadIdx.x;
    const bool isL2 = blockIdx.x >= 64;
    const int u0 = (blockIdx.x & 63) * 8;
    const int lane = tid & 31, warp = tid >> 5;
    const int c4 = lane & 3, q = lane >> 2;
    const int r0 = warp * 16 + q, r1 = r0 + 8;
    const int KP = isL2 ? K2P : K1P;
    const unsigned smem_base = (unsigned)__cvta_generic_to_shared(smf);
    const unsigned mbar_base = (unsigned)__cvta_generic_to_shared(mbf);

    if (tid == 0) {
        s_epoch0 = *(volatile unsigned*)&g_bar_epoch;
        asm volatile("mbarrier.init.shared.b64 [%0], 1;" :: "r"(mbar_base) : "memory");
        asm volatile("mbarrier.init.shared.b64 [%0], 1;" :: "r"(mbar_base + 8) : "memory");
        asm volatile("fence.proxy.async.shared::cta;" ::: "memory");
    }

    // ---- stage weight slice (tf32) + fused biases ----
    if (!isL2) {
        for (int idx = tid; idx < 32 * K1; idx += NTHR) {
            int r = idx / K1, k = idx - r * K1;
            int j = (r >> 3) * Hv + u0 + (r & 7);
            float wv = (k < DIN) ? w_ih1[j * DIN + k] : w_hh1[(size_t)j * Hv + (k - DIN)];
            sw[r * K1P + k] = f2tf(wv);
        }
        if (tid < 32) {
            int j = (tid >> 3) * Hv + u0 + (tid & 7);
            sb[tid] = b_ih1[j] + b_hh1[j];
        }
    } else {
        for (int idx = tid; idx < 32 * K2; idx += NTHR) {
            int r = idx >> 10, k = idx & 1023;
            int j = (r >> 3) * Hv + u0 + (r & 7);
            float wv = (k < Hv) ? w_ih2[(size_t)j * Hv + k] : w_hh2[(size_t)j * Hv + (k - Hv)];
            sw[r * K2P + k] = f2tf(wv);
        }
        if (tid < 32) {
            int j = (tid >> 3) * Hv + u0 + (tid & 7);
            sb[tid] = b_ih2[j] + b_hh2[j];
        }
    }
    for (int i = tid; i < 128 * 8; i += NTHR) sc[i] = 0.0f;

    // ---- zero initial shared state ----
    for (int idx = blockIdx.x * NTHR + tid; idx < 2 * 8 * CHUNK_W; idx += NCTA * NTHR)
        ((float*)g_h1)[idx] = 0.0f;
    for (int idx = blockIdx.x * NTHR + tid; idx < 8 * CHUNK_W; idx += NCTA * NTHR)
        g_h2all[idx] = 0.0f;
    __syncthreads();
    unsigned bar = s_epoch0;
    gridbar(++bar);

    unsigned ph0 = 0, ph1 = 0;
    const int ch = u0 >> 6, colbase = u0 & 63;

    for (int p = 0; p <= Tv; p++) {
        const bool active = isL2 ? (p >= 1) : (p < Tv);
        if (active) {
            const int NCH = isL2 ? 16 : 9;
            const float* srcA;
            const float* srcB;
            if (isL2) {
                srcA = &g_h1[(p - 1) & 1][0][0][0];
                srcB = g_h2all + (size_t)(p - 1) * 8 * CHUNK_W;
            } else {
                srcA = g_xT + (size_t)p * CHUNK_W;
                srcB = &g_h1[(p - 1) & 1][0][0][0];
            }
            // chunk c source:
            //   L1: c==0 -> xT;      c in 1..8 -> h1 chunk c-1
            //   L2: c in 0..7 -> h1 chunk c; c in 8..15 -> h2prev chunk c-8
            auto csrc = [&](int c) -> const float* {
                if (!isL2) return (c == 0) ? srcA : srcB + (size_t)(c - 1) * CHUNK_W;
                return (c < 8) ? srcA + (size_t)c * CHUNK_W : srcB + (size_t)(c - 8) * CHUNK_W;
            };

            float acc[4][4];
#pragma unroll
            for (int g = 0; g < 4; g++) {
                float b0 = sb[g * 8 + 2 * c4], b1 = sb[g * 8 + 2 * c4 + 1];
                acc[g][0] = b0; acc[g][1] = b1; acc[g][2] = b0; acc[g][3] = b1;
            }

            if (tid == 0) {
                issue_chunk(smem_base, csrc(0), mbar_base);
                issue_chunk(smem_base + CHUNK_BYTES, csrc(1), mbar_base + 8);
            }
            for (int c = 0; c < NCH; c++) {
                const int bsel = c & 1;
                mbar_wait(mbar_base + bsel * 8, (bsel ? ph1 : ph0) & 1);
                if (bsel) ph1++; else ph0++;

                const float* ap = chunks + bsel * CHUNK_W + r0 * CHW + c4;
                const int kb = c * 64;
#pragma unroll
                for (int kc = 0; kc < 64; kc += 8) {
                    unsigned a0 = f2tf(ap[kc]);
                    unsigned a1 = f2tf(ap[kc + 8 * CHW]);
                    unsigned a2 = f2tf(ap[kc + 4]);
                    unsigned a3 = f2tf(ap[kc + 4 + 8 * CHW]);
#pragma unroll
                    for (int g = 0; g < 4; g++) {
                        const unsigned* bp = sw + (g * 8 + q) * KP + kb + kc + c4;
                        unsigned b0 = bp[0], b1 = bp[4];
                        asm volatile(
                            "mma.sync.aligned.m16n8k8.row.col.f32.tf32.tf32.f32 "
                            "{%0,%1,%2,%3},{%4,%5,%6,%7},{%8,%9},{%0,%1,%2,%3};"
                            : "+f"(acc[g][0]), "+f"(acc[g][1]), "+f"(acc[g][2]), "+f"(acc[g][3])
                            : "r"(a0), "r"(a1), "r"(a2), "r"(a3), "r"(b0), "r"(b1));
                    }
                }
                if (c + 2 <= NCH - 1) {
                    __syncthreads();   // all warps done with this buffer
                    if (tid == 0) issue_chunk(smem_base + bsel * CHUNK_BYTES, csrc(c + 2),
                                              mbar_base + bsel * 8);
                }
            }

            // ---- epilogue ----
            float* hout = isL2
                ? g_h2all + ((size_t)p * 8 + ch) * CHUNK_W + colbase
                : &g_h1[p & 1][ch][0][colbase];
#pragma unroll
            for (int jj = 0; jj < 2; jj++) {
                int ul = 2 * c4 + jj;
#pragma unroll
                for (int rr = 0; rr < 2; rr++) {
                    int row = rr ? r1 : r0;
                    int qi = rr * 2 + jj;
                    float iv = sigm(acc[0][qi]);
                    float fv = sigm(acc[1][qi]);
                    float gv = tanh_(acc[2][qi]);
                    float ov = sigm(acc[3][qi]);
                    float cn = fv * sc[row * 8 + ul] + iv * gv;
                    sc[row * 8 + ul] = cn;
                    hout[(size_t)row * CHW + ul] = ov * tanh_(cn);
                }
            }
        }
        gridbar(++bar);
    }
}

// Post-pass: out[b][t][o] = h2(t)[b] . w_out[o] + b_out[o]
__global__ void __launch_bounds__(256)
out_gemm(const float* __restrict__ w_out, const float* __restrict__ b_out,
         float* __restrict__ out) {
    __shared__ __align__(16) float As[32 * CHW];  // [k][t]
    __shared__ __align__(16) float Bs[32 * CHW];  // [k][o]
    const int b = blockIdx.y;
    const int t0 = blockIdx.x * 64;
    const int tx = threadIdx.x;
    const int to = (tx & 15) * 4;
    const int tt = (tx >> 4) * 4;
    float acc[4][4] = {};
    for (int k0 = 0; k0 < Hv; k0 += 32) {
        for (int i = tx; i < 512; i += 256) {
            int row = i >> 3, kq = (i & 7) * 4;
            const float* src = g_h2all + ((size_t)(t0 + row + 1) * 8 + (k0 >> 6)) * CHUNK_W
                             + (size_t)b * CHW + (k0 & 63) + kq;
            float4 v = *(const float4*)src;
            As[(kq + 0) * CHW + row] = v.x;
            As[(kq + 1) * CHW + row] = v.y;
            As[(kq + 2) * CHW + row] = v.z;
            As[(kq + 3) * CHW + row] = v.w;
        }
        for (int i = tx; i < 512; i += 256) {
            int o = i >> 3, kq = (i & 7) * 4;
            float4 v = *(const float4*)(w_out + (size_t)o * Hv + k0 + kq);
            Bs[(kq + 0) * CHW + o] = v.x;
            Bs[(kq + 1) * CHW + o] = v.y;
            Bs[(kq + 2) * CHW + o] = v.z;
            Bs[(kq + 3) * CHW + o] = v.w;
        }
        __syncthreads();
#pragma unroll
        for (int k = 0; k < 32; k++) {
            float4 a = *(const float4*)(As + k * CHW + tt);
            float4 w = *(const float4*)(Bs + k * CHW + to);
            acc[0][0] = fmaf(a.x, w.x, acc[0][0]); acc[0][1] = fmaf(a.x, w.y, acc[0][1]);
            acc[0][2] = fmaf(a.x, w.z, acc[0][2]); acc[0][3] = fmaf(a.x, w.w, acc[0][3]);
            acc[1][0] = fmaf(a.y, w.x, acc[1][0]); acc[1][1] = fmaf(a.y, w.y, acc[1][1]);
            acc[1][2] = fmaf(a.y, w.z, acc[1][2]); acc[1][3] = fmaf(a.y, w.w, acc[1][3]);
            acc[2][0] = fmaf(a.z, w.x, acc[2][0]); acc[2][1] = fmaf(a.z, w.y, acc[2][1]);
            acc[2][2] = fmaf(a.z, w.z, acc[2][2]); acc[2][3] = fmaf(a.z, w.w, acc[2][3]);
            acc[3][0] = fmaf(a.w, w.x, acc[3][0]); acc[3][1] = fmaf(a.w, w.y, acc[3][1]);
            acc[3][2] = fmaf(a.w, w.z, acc[3][2]); acc[3][3] = fmaf(a.w, w.w, acc[3][3]);
        }
        __syncthreads();
    }
    float bo0 = b_out[to + 0], bo1 = b_out[to + 1], bo2 = b_out[to + 2], bo3 = b_out[to + 3];
#pragma unroll
    for (int i = 0; i < 4; i++) {
        float4 r;
        r.x = acc[i][0] + bo0; r.y = acc[i][1] + bo1;
        r.z = acc[i][2] + bo2; r.w = acc[i][3] + bo3;
        *(float4*)(out + ((size_t)b * Tv + t0 + tt + i) * DOUT + to) = r;
    }
}

extern "C" void kernel_launch(void* const* d_in, const int* in_sizes, int n_in,
                              void* d_out, int out_size) {
    (void)in_sizes; (void)n_in; (void)out_size;
    const float* x     = (const float*)d_in[0];
    const float* w_ih1 = (const float*)d_in[1];
    const float* w_hh1 = (const float*)d_in[2];
    const float* b_ih1 = (const float*)d_in[3];
    const float* b_hh1 = (const float*)d_in[4];
    const float* w_ih2 = (const float*)d_in[5];
    const float* w_hh2 = (const float*)d_in[6];
    const float* b_ih2 = (const float*)d_in[7];
    const float* b_hh2 = (const float*)d_in[8];
    const float* w_out = (const float*)d_in[9];
    const float* b_out = (const float*)d_in[10];

    xpose<<<Tv, 256>>>(x);
    cudaFuncSetAttribute(lstm_kernel, cudaFuncAttributeMaxDynamicSharedMemorySize, SMEM_BYTES);
    lstm_kernel<<<NCTA, NTHR, SMEM_BYTES>>>(w_ih1, w_hh1, b_ih1, b_hh1,
                                            w_ih2, w_hh2, b_ih2, b_hh2);
    out_gemm<<<dim3(Tv / 64, Bv), 256>>>(w_out, b_out, (float*)d_out);
}